// round 13
// baseline (speedup 1.0000x reference)
#include <cuda_runtime.h>
#include <math.h>

#define BN_EPS 1e-5f

// packed f32x2 helpers (sm_100+; only reachable via PTX; add/mul/fma only)
#define F32X2_PACK(o, lo, hi)  asm("mov.b64 %0, {%1, %2};" : "=l"(o) : "f"(lo), "f"(hi))
#define F32X2_UNPACK(lo, hi, i) asm("mov.b64 {%0, %1}, %2;" : "=f"(lo), "=f"(hi) : "l"(i))
#define F32X2_ADD(o, a, b)     asm("add.rn.f32x2 %0, %1, %2;" : "=l"(o) : "l"(a), "l"(b))
#define F32X2_MUL(o, a, b)     asm("mul.rn.f32x2 %0, %1, %2;" : "=l"(o) : "l"(a), "l"(b))
#define F32X2_FMA(o, a, b, c)  asm("fma.rn.f32x2 %0, %1, %2, %3;" : "=l"(o) : "l"(a), "l"(b), "l"(c))

// ---------------- scratch (static device globals; no allocations) ----------------
__device__ float g_ybuf[16*1024*16*64];   // carved: stage0 ybuf | ymax | ymin | part | part2
__device__ float g_h0[16*4096*32];
__device__ float g_p1[16*1024*3];
__device__ float g_h1[16*1024*64];
__device__ float g_p2[16*256*3];
__device__ float g_h2[16*256*128];
__device__ float g_p3[16*64*3];
__device__ float g_h3[16*64*256];
__device__ float g_p4[16*16*3];
__device__ float g_h4[16*16*512];
__device__ int   g_knn[16*1024*16];
__device__ float g_part[512*2*512];       // stage0 partials [NB][2][D]
__device__ float g_scale[512];
__device__ float g_shift[512];
__device__ int   g_prog[16];              // fps1 per-batch row progress (monotone per run;
                                          // stale-high across replays is safe: rewrites are bit-identical)

// ---------------- side stream + fork/join events (created at load, before checkpoints) ----------------
struct GpuSync {
    cudaStream_t sb = nullptr;
    cudaEvent_t fork = nullptr, e1 = nullptr, e2 = nullptr, e3 = nullptr, e4 = nullptr;
    bool ok = false;
    GpuSync() {
        ok = (cudaStreamCreateWithFlags(&sb, cudaStreamNonBlocking) == cudaSuccess)
          && (cudaEventCreateWithFlags(&fork, cudaEventDisableTiming) == cudaSuccess)
          && (cudaEventCreateWithFlags(&e1,   cudaEventDisableTiming) == cudaSuccess)
          && (cudaEventCreateWithFlags(&e2,   cudaEventDisableTiming) == cudaSuccess)
          && (cudaEventCreateWithFlags(&e3,   cudaEventDisableTiming) == cudaSuccess)
          && (cudaEventCreateWithFlags(&e4,   cudaEventDisableTiming) == cudaSuccess);
    }
};
static GpuSync g_sync;

// ---------------- FPS (R9-proven): one block per batch, f32x2 distance loop ----------------
// prog != nullptr (fps1 only): publish per-batch row progress with st.release.gpu (no stall).
template<int N, int T>
__global__ void fps_kernel(const float* __restrict__ p, int M, float* __restrict__ newp,
                           int* prog) {
    constexpr int NPT = N / T;
    constexpr int NW  = T / 32;
    const int b = blockIdx.x, tid = threadIdx.x;
    const float* pb = p + (size_t)b * N * 3;
    __shared__ unsigned s_wd[16];
    __shared__ int      s_wi[16];
    __shared__ float    s_b[3];
    if (tid == 0) {
        s_b[0] = pb[0]; s_b[1] = pb[1]; s_b[2] = pb[2];
        float* o = newp + (size_t)b * M * 3;
        o[0] = pb[0]; o[1] = pb[1]; o[2] = pb[2];
        if (prog) asm volatile("st.release.gpu.b32 [%0], %1;" :: "l"(prog + b), "r"(0) : "memory");
    }
    __syncthreads();
    float bx = s_b[0], by = s_b[1], bz = s_b[2];

    if constexpr (NPT >= 2) {
        constexpr int NP2 = NPT / 2;
        unsigned long long px2[NP2], py2[NP2], pz2[NP2];
        float md[NPT];
#pragma unroll
        for (int a = 0; a < NP2; a++) {
            int g0 = (2*a)   * T + tid;
            int g1 = (2*a+1) * T + tid;
            F32X2_PACK(px2[a], pb[g0*3+0], pb[g1*3+0]);
            F32X2_PACK(py2[a], pb[g0*3+1], pb[g1*3+1]);
            F32X2_PACK(pz2[a], pb[g0*3+2], pb[g1*3+2]);
            md[2*a] = INFINITY; md[2*a+1] = INFINITY;
        }
        for (int t = 1; t < M; t++) {
            float nbx = -bx, nby = -by, nbz = -bz;
            unsigned long long nbx2, nby2, nbz2;
            F32X2_PACK(nbx2, nbx, nbx);
            F32X2_PACK(nby2, nby, nby);
            F32X2_PACK(nbz2, nbz, nbz);
            float best = 0.0f; int besti = 0x7fffffff;
#pragma unroll
            for (int a = 0; a < NP2; a++) {
                unsigned long long dx2, dy2, dz2, t2;
                F32X2_ADD(dx2, px2[a], nbx2);           // lx - bx (IEEE-identical to sub)
                F32X2_ADD(dy2, py2[a], nby2);
                F32X2_ADD(dz2, pz2[a], nbz2);
                F32X2_MUL(t2, dz2, dz2);                // dz*dz
                F32X2_FMA(t2, dy2, dy2, t2);            // dy*dy + .
                F32X2_FMA(t2, dx2, dx2, t2);            // dx*dx + .  (== R4 fmaf chain)
                float d0, d1;
                F32X2_UNPACK(d0, d1, t2);
                float v0 = fminf(md[2*a], d0);   md[2*a]   = v0;
                float v1 = fminf(md[2*a+1], d1); md[2*a+1] = v1;
                int g0 = (2*a)   * T + tid;
                int g1 = (2*a+1) * T + tid;
                if (v0 > best || (v0 == best && g0 < besti)) { best = v0; besti = g0; }
                if (v1 > best || (v1 == best && g1 < besti)) { best = v1; besti = g1; }
            }
            // warp argmax via REDUX (dists >= 0 so float bits are order-preserving)
            unsigned bb = __float_as_uint(best);
            unsigned mb = __reduce_max_sync(0xffffffffu, bb);
            int cand = (bb == mb) ? besti : 0x7fffffff;
            int wbi = __reduce_min_sync(0xffffffffu, cand);
            if ((tid & 31) == 0) { s_wd[tid >> 5] = mb; s_wi[tid >> 5] = wbi; }
            __syncthreads();
            if (tid < 32) {
                unsigned u = (tid < NW) ? s_wd[tid] : 0u;
                int      ii = (tid < NW) ? s_wi[tid] : 0x7fffffff;
                unsigned m2 = __reduce_max_sync(0xffffffffu, u);
                int c2 = (u == m2) ? ii : 0x7fffffff;
                int win = __reduce_min_sync(0xffffffffu, c2);
                if (tid == 0) {
                    const float* wp = pb + (size_t)win * 3;   // L1-hot
                    float cx = wp[0], cy = wp[1], cz = wp[2];
                    s_b[0] = cx; s_b[1] = cy; s_b[2] = cz;
                    float* o = newp + ((size_t)b * M + t) * 3;
                    o[0] = cx; o[1] = cy; o[2] = cz;
                    if (prog) asm volatile("st.release.gpu.b32 [%0], %1;" :: "l"(prog + b), "r"(t) : "memory");
                }
            }
            __syncthreads();
            bx = s_b[0]; by = s_b[1]; bz = s_b[2];
        }
    } else {
        // scalar path (NPT == 1): identical to R4
        float lx = pb[tid*3+0], ly = pb[tid*3+1], lz = pb[tid*3+2], md = INFINITY;
        for (int t = 1; t < M; t++) {
            float best = 0.0f; int besti = 0x7fffffff;
            float dx = lx-bx, dy = ly-by, dz = lz-bz;
            float d = fmaf(dx, dx, fmaf(dy, dy, dz*dz));
            float v = fminf(md, d);
            md = v;
            if (v > best || (v == best && tid < besti)) { best = v; besti = tid; }
            unsigned bb = __float_as_uint(best);
            unsigned mb = __reduce_max_sync(0xffffffffu, bb);
            int cand = (bb == mb) ? besti : 0x7fffffff;
            int wbi = __reduce_min_sync(0xffffffffu, cand);
            if ((tid & 31) == 0) { s_wd[tid >> 5] = mb; s_wi[tid >> 5] = wbi; }
            __syncthreads();
            if (tid < 32) {
                unsigned u = (tid < NW) ? s_wd[tid] : 0u;
                int      ii = (tid < NW) ? s_wi[tid] : 0x7fffffff;
                unsigned m2 = __reduce_max_sync(0xffffffffu, u);
                int c2 = (u == m2) ? ii : 0x7fffffff;
                int win = __reduce_min_sync(0xffffffffu, c2);
                if (tid == 0) {
                    const float* wp = pb + (size_t)win * 3;
                    float cx = wp[0], cy = wp[1], cz = wp[2];
                    s_b[0] = cx; s_b[1] = cy; s_b[2] = cz;
                    float* o = newp + ((size_t)b * M + t) * 3;
                    o[0] = cx; o[1] = cy; o[2] = cz;
                }
            }
            __syncthreads();
            bx = s_b[0]; by = s_b[1]; bz = s_b[2];
        }
    }
}

// ---------------- kNN: R12 body; optional spin-gate on fps1 progress ----------------
__global__ void knn_kernel(const float* __restrict__ p, const float* __restrict__ newp,
                           int N, int M, int* __restrict__ knn, const int* prog) {
    extern __shared__ float dist[];          // N floats
    __shared__ float s_tmin[128];
    __shared__ int   s_tidx[128];
    __shared__ int   s_win;
    const int q = blockIdx.x;
    const int b = q / M;
    const int tid = threadIdx.x;
    if (prog) {                              // wait until fps1 has published our query row
        if (tid == 0) {
            const int m = q - b * M;
            int pr;
            do {
                asm volatile("ld.acquire.gpu.b32 %0, [%1];" : "=r"(pr) : "l"(prog + b) : "memory");
                if (pr >= m) break;
                __nanosleep(128);
            } while (true);
        }
        __syncthreads();
    }
    const float* pb = p + (size_t)b * N * 3;
    const float qx = newp[q*3+0], qy = newp[q*3+1], qz = newp[q*3+2];
    float bd = INFINITY; int bi = 0x7fffffff;
    // packed init: pairs (n, n+128); (p-q)^2 is bit-identical to (q-p)^2
    {
        float nqx = -qx, nqy = -qy, nqz = -qz;
        unsigned long long nqx2, nqy2, nqz2;
        F32X2_PACK(nqx2, nqx, nqx);
        F32X2_PACK(nqy2, nqy, nqy);
        F32X2_PACK(nqz2, nqz, nqz);
        int n = tid;
        for (; n + 128 < N; n += 256) {
            int n1 = n + 128;
            unsigned long long px2, py2, pz2, dx2, dy2, dz2, t2;
            F32X2_PACK(px2, pb[n*3+0], pb[n1*3+0]);
            F32X2_PACK(py2, pb[n*3+1], pb[n1*3+1]);
            F32X2_PACK(pz2, pb[n*3+2], pb[n1*3+2]);
            F32X2_ADD(dx2, px2, nqx2);       // p - q
            F32X2_ADD(dy2, py2, nqy2);
            F32X2_ADD(dz2, pz2, nqz2);
            F32X2_MUL(t2, dz2, dz2);
            F32X2_FMA(t2, dy2, dy2, t2);
            F32X2_FMA(t2, dx2, dx2, t2);     // == fmaf(dx,dx,fmaf(dy,dy,dz*dz))
            float d0, d1;
            F32X2_UNPACK(d0, d1, t2);
            dist[n]  = d0;
            dist[n1] = d1;
            if (d0 < bd) { bd = d0; bi = n;  }   // ascending n -> first-index ties
            if (d1 < bd) { bd = d1; bi = n1; }
        }
        for (; n < N; n += 128) {            // scalar tail (N < 256 stages)
            float dx = qx - pb[n*3+0], dy = qy - pb[n*3+1], dz = qz - pb[n*3+2];
            float d = fmaf(dx, dx, fmaf(dy, dy, dz*dz));
            dist[n] = d;
            if (d < bd) { bd = d; bi = n; }
        }
    }
    s_tmin[tid] = bd; s_tidx[tid] = bi;
    __syncthreads();
    for (int r = 0; ; r++) {
        if (tid < 32) {
            float m0 = s_tmin[tid]; int i0 = s_tidx[tid];
#pragma unroll
            for (int off = 32; off < 128; off += 32) {
                float mm = s_tmin[tid + off]; int ii = s_tidx[tid + off];
                if (mm < m0 || (mm == m0 && ii < i0)) { m0 = mm; i0 = ii; }
            }
            unsigned b0 = __float_as_uint(m0);
            unsigned mb = __reduce_min_sync(0xffffffffu, b0);
            int cand = (b0 == mb) ? i0 : 0x7fffffff;
            int win = __reduce_min_sync(0xffffffffu, cand);
            if (tid == 0) { knn[(size_t)q*16 + r] = win; s_win = win; }
        }
        __syncthreads();
        if (r == 15) break;
        int win = s_win;
        if ((win & 127) == tid) {            // owner rescans its slice
            dist[win] = INFINITY;
            float nb = INFINITY; int ni = 0x7fffffff;
            for (int n = tid; n < N; n += 128) {
                float d = dist[n];
                if (d < nb) { nb = d; ni = n; }
            }
            s_tmin[tid] = nb; s_tidx[tid] = ni;
        }
        __syncthreads();
    }
}

// ---------------- fused grouped GEMM + max/min over k + per-block channel stats ----------------
__global__ void td_gemm_fused(const float* __restrict__ p, const float* __restrict__ h,
                              const float* __restrict__ newp, const int* __restrict__ knn,
                              const float* __restrict__ W, int N, int M, int C, int D,
                              float* __restrict__ ymax, float* __restrict__ ymin,
                              float* __restrict__ part) {
    extern __shared__ float feat[];          // 16*(C+3)
    __shared__ int   s_knn[16];
    __shared__ float s_np[3];
    const int q = blockIdx.x;
    const int b = q / M;
    const int t = threadIdx.x;               // D threads, one per output channel
    if (t < 16) s_knn[t] = knn[(size_t)q*16 + t];
    if (t < 3)  s_np[t]  = newp[q*3 + t];
    __syncthreads();
    const int F = C + 3;
    const float* pb = p + (size_t)b * N * 3;
    const float* hb = h + (size_t)b * N * C;
    for (int e = t; e < 16 * F; e += D) {
        int k = e / F, c = e - k * F;
        int n = s_knn[k];
        feat[e] = (c < 3) ? (pb[n*3 + c] - s_np[c]) : hb[(size_t)n * C + (c - 3)];
    }
    __syncthreads();
    float acc[16];
#pragma unroll
    for (int k = 0; k < 16; k++) acc[k] = 0.f;
#pragma unroll 2
    for (int c = 0; c < F; c++) {
        float w = W[(size_t)c * D + t];      // loaded once per c
#pragma unroll
        for (int k = 0; k < 16; k++) acc[k] += feat[k*F + c] * w;   // LDS broadcast
    }
    float mx = -INFINITY, mn = INFINITY, s = 0.f, s2 = 0.f;
#pragma unroll
    for (int k = 0; k < 16; k++) {
        float v = acc[k];
        mx = fmaxf(mx, v); mn = fminf(mn, v);
        s += v; s2 += v * v;
    }
    ymax[(size_t)q * D + t] = mx;
    ymin[(size_t)q * D + t] = mn;
    part[(size_t)q * 2 * D + t]     = s;
    part[(size_t)q * 2 * D + D + t] = s2;
}

// ---------------- stats tree: level-1 reduce of per-block partials ----------------
__global__ void stats_reduce(const float* __restrict__ part, int Q, int D,
                             float* __restrict__ out) {
    const int t = threadIdx.x;               // D threads
    const int per = (Q + gridDim.x - 1) / gridDim.x;
    const int r0 = blockIdx.x * per;
    const int r1 = min(r0 + per, Q);
    float s = 0.f, s2 = 0.f;
    for (int r = r0; r < r1; r++) {
        s  += part[(size_t)r * 2 * D + t];
        s2 += part[(size_t)r * 2 * D + D + t];
    }
    out[(size_t)blockIdx.x * 2 * D + t]     = s;
    out[(size_t)blockIdx.x * 2 * D + D + t] = s2;
}

__global__ void stats_final(const float* __restrict__ part, int NB, int D, float cnt,
                            const float* __restrict__ g, const float* __restrict__ bta,
                            float* __restrict__ scale, float* __restrict__ shift) {
    const int c = threadIdx.x;
    if (c >= D) return;
    float S = 0.f, Q2 = 0.f;
    for (int i = 0; i < NB; i++) {
        S  += part[(size_t)i * 2 * D + c];
        Q2 += part[(size_t)i * 2 * D + D + c];
    }
    float m = S / cnt;
    float v = Q2 / cnt - m * m;
    float sc = g[c] * rsqrtf(v + BN_EPS);
    scale[c] = sc;
    shift[c] = bta[c] - m * sc;
}

// ---------------- apply BN+ReLU to the sign-appropriate extremum ----------------
__global__ void td_norm(const float* __restrict__ ymax, const float* __restrict__ ymin,
                        const float* __restrict__ scale, const float* __restrict__ shift,
                        int total, int D, float* __restrict__ hout) {
    int i = blockIdx.x * 256 + threadIdx.x;
    if (i >= total) return;
    int d = i % D;
    float sc = scale[d];
    float v = (sc >= 0.f) ? ymax[i] : ymin[i];
    hout[i] = fmaxf(0.f, sc * v + shift[d]);
}

// ---------------- stage 0: h = p @ W1 (3->32) ----------------
__global__ void s0_gemm(const float* __restrict__ x, const float* __restrict__ W1,
                        float* __restrict__ y) {
    int i = blockIdx.x * 256 + threadIdx.x;
    if (i >= 16*4096*32) return;
    int pt = i >> 5, c = i & 31;
    const float* xp = x + (size_t)pt * 3;
    y[i] = xp[0]*W1[c] + xp[1]*W1[32+c] + xp[2]*W1[64+c];
}

__global__ void stats_partial(const float* __restrict__ y, int Q, int D, float* __restrict__ part) {
    const int NB = gridDim.x;
    const int rpb = (Q + NB - 1) / NB;
    const int r0 = blockIdx.x * rpb;
    const int r1 = min(r0 + rpb, Q);
    __shared__ float ss[256], sq[256];
    const int tid = threadIdx.x;
    const int rpi = 256 / D;
    const int c = tid % D;
    const int ro = tid / D;
    float s = 0.f, q2 = 0.f;
    for (int r = r0 + ro; r < r1; r += rpi) {
        float v = y[(size_t)r * D + c]; s += v; q2 += v * v;
    }
    ss[tid] = s; sq[tid] = q2;
    __syncthreads();
    if (tid < D) {
        for (int o = 1; o < rpi; o++) { s += ss[tid + o*D]; q2 += sq[tid + o*D]; }
        part[(size_t)blockIdx.x * 2 * D + tid]     = s;
        part[(size_t)blockIdx.x * 2 * D + D + tid] = q2;
    }
}

__global__ void normalize_kernel(const float* __restrict__ y, const float* __restrict__ scale,
                                 const float* __restrict__ shift, int total, int D,
                                 float* __restrict__ out) {
    int i = blockIdx.x * 256 + threadIdx.x;
    if (i >= total) return;
    int c = i % D;
    out[i] = fmaxf(0.f, y[i] * scale[c] + shift[c]);
}

// ---------------- classifier head: single block, channel-per-thread ----------------
__global__ void classifier_kernel(const float* __restrict__ h4,
                                  const float* __restrict__ Wc1, const float* __restrict__ bc1,
                                  const float* __restrict__ gc1, const float* __restrict__ hc1,
                                  const float* __restrict__ Wc2, const float* __restrict__ bc2,
                                  const float* __restrict__ gc2, const float* __restrict__ hc2,
                                  const float* __restrict__ Wc3, const float* __restrict__ bc3,
                                  float* __restrict__ out) {
    __shared__ float sb[12288];
    float* z  = sb;
    float* z1 = sb + 8192;
    const int t = threadIdx.x;  // 256 threads
    for (int e = t; e < 8192; e += 256) {
        int b = e >> 9, c = e & 511;
        float s = 0.f;
        for (int k = 0; k < 16; k++) s += h4[((size_t)(b*16 + k))*512 + c];
        z[e] = s * (1.f/16.f);
    }
    __syncthreads();
    {
        float acc[16];
#pragma unroll
        for (int b = 0; b < 16; b++) acc[b] = bc1[t];
        for (int i = 0; i < 512; i++) {
            float w = Wc1[(size_t)i*256 + t];
#pragma unroll
            for (int b = 0; b < 16; b++) acc[b] += z[b*512 + i] * w;
        }
        float m = 0.f;
#pragma unroll
        for (int b = 0; b < 16; b++) m += acc[b];
        m *= (1.f/16.f);
        float v = 0.f;
#pragma unroll
        for (int b = 0; b < 16; b++) { float d = acc[b]-m; v += d*d; }
        v *= (1.f/16.f);
        float sc = gc1[t] * rsqrtf(v + BN_EPS);
        float sh = hc1[t] - m * sc;
#pragma unroll
        for (int b = 0; b < 16; b++) z1[b*256 + t] = fmaxf(0.f, acc[b]*sc + sh);
    }
    __syncthreads();
    float* z2 = sb;
    if (t < 128) {
        float acc[16];
#pragma unroll
        for (int b = 0; b < 16; b++) acc[b] = bc2[t];
        for (int i = 0; i < 256; i++) {
            float w = Wc2[(size_t)i*128 + t];
#pragma unroll
            for (int b = 0; b < 16; b++) acc[b] += z1[b*256 + i] * w;
        }
        float m = 0.f;
#pragma unroll
        for (int b = 0; b < 16; b++) m += acc[b];
        m *= (1.f/16.f);
        float v = 0.f;
#pragma unroll
        for (int b = 0; b < 16; b++) { float d = acc[b]-m; v += d*d; }
        v *= (1.f/16.f);
        float sc = gc2[t] * rsqrtf(v + BN_EPS);
        float sh = hc2[t] - m * sc;
#pragma unroll
        for (int b = 0; b < 16; b++) z2[b*128 + t] = fmaxf(0.f, acc[b]*sc + sh);
    }
    __syncthreads();
    if (t < 40) {
        float acc[16];
#pragma unroll
        for (int b = 0; b < 16; b++) acc[b] = bc3[t];
        for (int i = 0; i < 128; i++) {
            float w = Wc3[(size_t)i*40 + t];
#pragma unroll
            for (int b = 0; b < 16; b++) acc[b] += z2[b*128 + i] * w;
        }
#pragma unroll
        for (int b = 0; b < 16; b++) out[b*40 + t] = acc[b];
    }
}

// ---------------- driver ----------------
extern "C" void kernel_launch(void* const* d_in, const int* in_sizes, int n_in,
                              void* d_out, int out_size) {
    (void)in_sizes; (void)n_in; (void)out_size;
    const float* x   = (const float*)d_in[0];
    const float* W1  = (const float*)d_in[1];
    const float* g1  = (const float*)d_in[2];
    const float* b1  = (const float*)d_in[3];
    const float* W2  = (const float*)d_in[4];
    const float* g2  = (const float*)d_in[5];
    const float* b2  = (const float*)d_in[6];
    const float* W3  = (const float*)d_in[7];
    const float* g3  = (const float*)d_in[8];
    const float* b3  = (const float*)d_in[9];
    const float* W4  = (const float*)d_in[10];
    const float* g4  = (const float*)d_in[11];
    const float* b4  = (const float*)d_in[12];
    const float* W5  = (const float*)d_in[13];
    const float* g5  = (const float*)d_in[14];
    const float* b5  = (const float*)d_in[15];
    const float* Wc1 = (const float*)d_in[16];
    const float* bc1 = (const float*)d_in[17];
    const float* gc1 = (const float*)d_in[18];
    const float* hc1 = (const float*)d_in[19];
    const float* Wc2 = (const float*)d_in[20];
    const float* bc2 = (const float*)d_in[21];
    const float* gc2 = (const float*)d_in[22];
    const float* hc2 = (const float*)d_in[23];
    const float* Wc3 = (const float*)d_in[24];
    const float* bc3 = (const float*)d_in[25];
    float* out = (float*)d_out;

    float *ybuf, *h0, *p1, *h1, *p2, *h2, *p3, *h3, *p4, *h4, *part0, *scale, *shift;
    int *knn, *prog;
    cudaGetSymbolAddress((void**)&ybuf,  g_ybuf);
    cudaGetSymbolAddress((void**)&h0,    g_h0);
    cudaGetSymbolAddress((void**)&p1,    g_p1);
    cudaGetSymbolAddress((void**)&h1,    g_h1);
    cudaGetSymbolAddress((void**)&p2,    g_p2);
    cudaGetSymbolAddress((void**)&h2,    g_h2);
    cudaGetSymbolAddress((void**)&p3,    g_p3);
    cudaGetSymbolAddress((void**)&h3,    g_h3);
    cudaGetSymbolAddress((void**)&p4,    g_p4);
    cudaGetSymbolAddress((void**)&h4,    g_h4);
    cudaGetSymbolAddress((void**)&knn,   g_knn);
    cudaGetSymbolAddress((void**)&part0, g_part);
    cudaGetSymbolAddress((void**)&scale, g_scale);
    cudaGetSymbolAddress((void**)&shift, g_shift);
    cudaGetSymbolAddress((void**)&prog,  g_prog);

    // carve scratch from ybuf (temporally disjoint with stage0's use of ybuf[0..2M))
    float* ymax  = ybuf;                       // <= 1,048,576 floats
    float* ymin  = ybuf + 1048576;
    float* part  = ybuf + 2097152;             // <= 2,097,152 floats (TD1)
    float* part2 = ybuf + 4194304;             // <= 65,536 floats
    const int NR = 64;

    const bool ov = g_sync.ok;
    cudaStream_t SB = ov ? g_sync.sb : 0;

    // ---- fork: FPS chain on side stream (positions only; independent of features) ----
    if (ov) { cudaEventRecord(g_sync.fork, 0); cudaStreamWaitEvent(SB, g_sync.fork, 0); }
    fps_kernel<4096, 512><<<16, 512, 0, SB>>>(x, 1024, p1, prog);  // publishes row progress
    if (ov) cudaEventRecord(g_sync.e1, SB);
    fps_kernel<1024, 256><<<16, 256, 0, SB>>>(p1, 256, p2, nullptr);
    if (ov) cudaEventRecord(g_sync.e2, SB);
    fps_kernel<256, 256><<<16, 256, 0, SB>>>(p2, 64, p3, nullptr);
    if (ov) cudaEventRecord(g_sync.e3, SB);
    fps_kernel<64, 64><<<16, 64, 0, SB>>>(p3, 16, p4, nullptr);
    if (ov) cudaEventRecord(g_sync.e4, SB);

    // ---- main stream: stage 0 (overlaps fps1) ----
    s0_gemm<<<(16*4096*32 + 255)/256, 256>>>(x, W1, ybuf);
    stats_partial<<<512, 256>>>(ybuf, 16*4096, 32, part0);
    stats_final<<<1, 32>>>(part0, 512, 32, (float)(16*4096), g1, b1, scale, shift);
    normalize_kernel<<<(16*4096*32 + 255)/256, 256>>>(ybuf, scale, shift, 16*4096*32, 32, h0);

    // ---- TD1: 4096 -> 1024, C=32 -> D=64 ----
    // knn1 pipelines against fps1 via progress counter (no e1 wait): block q gates on row q%M.
    knn_kernel<<<16*1024, 128, 4096*4>>>(x, p1, 4096, 1024, knn, prog);
    td_gemm_fused<<<16*1024, 64, 16*35*4>>>(x, h0, p1, knn, W2, 4096, 1024, 32, 64, ymax, ymin, part);
    stats_reduce<<<NR, 64>>>(part, 16*1024, 64, part2);
    stats_final<<<1, 64>>>(part2, NR, 64, (float)(16*1024*16), g2, b2, scale, shift);
    td_norm<<<(16*1024*64 + 255)/256, 256>>>(ymax, ymin, scale, shift, 16*1024*64, 64, h1);

    // ---- TD2: 1024 -> 256, C=64 -> D=128 ----
    if (ov) cudaStreamWaitEvent(0, g_sync.e2, 0);
    knn_kernel<<<16*256, 128, 1024*4>>>(p1, p2, 1024, 256, knn, nullptr);
    td_gemm_fused<<<16*256, 128, 16*67*4>>>(p1, h1, p2, knn, W3, 1024, 256, 64, 128, ymax, ymin, part);
    stats_reduce<<<NR, 128>>>(part, 16*256, 128, part2);
    stats_final<<<1, 128>>>(part2, NR, 128, (float)(16*256*16), g3, b3, scale, shift);
    td_norm<<<(16*256*128 + 255)/256, 256>>>(ymax, ymin, scale, shift, 16*256*128, 128, h2);

    // ---- TD3: 256 -> 64, C=128 -> D=256 ----
    if (ov) cudaStreamWaitEvent(0, g_sync.e3, 0);
    knn_kernel<<<16*64, 128, 256*4>>>(p2, p3, 256, 64, knn, nullptr);
    td_gemm_fused<<<16*64, 256, 16*131*4>>>(p2, h2, p3, knn, W4, 256, 64, 128, 256, ymax, ymin, part);
    stats_reduce<<<NR, 256>>>(part, 16*64, 256, part2);
    stats_final<<<1, 256>>>(part2, NR, 256, (float)(16*64*16), g4, b4, scale, shift);
    td_norm<<<(16*64*256 + 255)/256, 256>>>(ymax, ymin, scale, shift, 16*64*256, 256, h3);

    // ---- TD4: 64 -> 16, C=256 -> D=512 (join: waits last side-stream event) ----
    if (ov) cudaStreamWaitEvent(0, g_sync.e4, 0);
    knn_kernel<<<16*16, 128, 64*4>>>(p3, p4, 64, 16, knn, nullptr);
    td_gemm_fused<<<16*16, 512, 16*259*4>>>(p3, h3, p4, knn, W5, 64, 16, 256, 512, ymax, ymin, part);
    stats_reduce<<<NR, 512>>>(part, 16*16, 512, part2);
    stats_final<<<1, 512>>>(part2, NR, 512, (float)(16*16*16), g5, b5, scale, shift);
    td_norm<<<(16*16*512 + 255)/256, 256>>>(ymax, ymin, scale, shift, 16*16*512, 512, h4);

    // ---- classifier head ----
    classifier_kernel<<<1, 256>>>(h4, Wc1, bc1, gc1, hc1, Wc2, bc2, gc2, hc2, Wc3, bc3, out);
}

// round 14
// speedup vs baseline: 1.8024x; 1.8024x over previous
#include <cuda_runtime.h>
#include <math.h>

#define BN_EPS 1e-5f

// packed f32x2 helpers (sm_100+; only reachable via PTX; add/mul/fma only)
#define F32X2_PACK(o, lo, hi)  asm("mov.b64 %0, {%1, %2};" : "=l"(o) : "f"(lo), "f"(hi))
#define F32X2_UNPACK(lo, hi, i) asm("mov.b64 {%0, %1}, %2;" : "=f"(lo), "=f"(hi) : "l"(i))
#define F32X2_ADD(o, a, b)     asm("add.rn.f32x2 %0, %1, %2;" : "=l"(o) : "l"(a), "l"(b))
#define F32X2_MUL(o, a, b)     asm("mul.rn.f32x2 %0, %1, %2;" : "=l"(o) : "l"(a), "l"(b))
#define F32X2_FMA(o, a, b, c)  asm("fma.rn.f32x2 %0, %1, %2, %3;" : "=l"(o) : "l"(a), "l"(b), "l"(c))

// ---------------- scratch (static device globals; no allocations) ----------------
__device__ float g_ybuf[16*1024*16*64];   // carved: stage0 ybuf | ymax | ymin | part | part2
__device__ float g_h0[16*4096*32];
__device__ float g_p1[16*1024*3];
__device__ float g_h1[16*1024*64];
__device__ float g_p2[16*256*3];
__device__ float g_h2[16*256*128];
__device__ float g_p3[16*64*3];
__device__ float g_h3[16*64*256];
__device__ float g_p4[16*16*3];
__device__ float g_h4[16*16*512];
__device__ int   g_knn[16*1024*16];
__device__ float g_part[512*2*512];       // stage0 partials [NB][2][D]
__device__ float g_scale[512];
__device__ float g_shift[512];

// ---------------- side stream + fork/join events (created at load, before checkpoints) ----------------
struct GpuSync {
    cudaStream_t sb = nullptr;
    cudaEvent_t fork = nullptr, e1 = nullptr, e2 = nullptr, e3 = nullptr, e4 = nullptr;
    bool ok = false;
    GpuSync() {
        ok = (cudaStreamCreateWithFlags(&sb, cudaStreamNonBlocking) == cudaSuccess)
          && (cudaEventCreateWithFlags(&fork, cudaEventDisableTiming) == cudaSuccess)
          && (cudaEventCreateWithFlags(&e1,   cudaEventDisableTiming) == cudaSuccess)
          && (cudaEventCreateWithFlags(&e2,   cudaEventDisableTiming) == cudaSuccess)
          && (cudaEventCreateWithFlags(&e3,   cudaEventDisableTiming) == cudaSuccess)
          && (cudaEventCreateWithFlags(&e4,   cudaEventDisableTiming) == cudaSuccess);
    }
};
static GpuSync g_sync;

// ---------------- FPS: f32x2 distance loop + single-barrier atomicMax(u64) argmax ----------------
// key = (dist_bits << 32) | (0x7fffffff - idx): max-key == max dist, first index on ties.
// slot==0 is exactly the old sentinel (best=0, besti=0x7fffffff). 4-slot rotation makes
// reset/atomic/read regions barrier-separated.
template<int N, int T>
__global__ void fps_kernel(const float* __restrict__ p, int M, float* __restrict__ newp) {
    constexpr int NPT = N / T;
    const int b = blockIdx.x, tid = threadIdx.x;
    const float* pb = p + (size_t)b * N * 3;
    __shared__ unsigned long long s_key[4];
    if (tid < 4) s_key[tid] = 0ull;
    if (tid == 0) {
        float* o = newp + (size_t)b * M * 3;
        o[0] = pb[0]; o[1] = pb[1]; o[2] = pb[2];
    }
    __syncthreads();
    float bx = pb[0], by = pb[1], bz = pb[2];

    if constexpr (NPT >= 2) {
        constexpr int NP2 = NPT / 2;
        unsigned long long px2[NP2], py2[NP2], pz2[NP2];
        float md[NPT];
#pragma unroll
        for (int a = 0; a < NP2; a++) {
            int g0 = (2*a)   * T + tid;
            int g1 = (2*a+1) * T + tid;
            F32X2_PACK(px2[a], pb[g0*3+0], pb[g1*3+0]);
            F32X2_PACK(py2[a], pb[g0*3+1], pb[g1*3+1]);
            F32X2_PACK(pz2[a], pb[g0*3+2], pb[g1*3+2]);
            md[2*a] = INFINITY; md[2*a+1] = INFINITY;
        }
        for (int t = 1; t < M; t++) {
            if (tid == 0) s_key[(t+2) & 3] = 0ull;     // pre-barrier reset for step t+2
            float nbx = -bx, nby = -by, nbz = -bz;
            unsigned long long nbx2, nby2, nbz2;
            F32X2_PACK(nbx2, nbx, nbx);
            F32X2_PACK(nby2, nby, nby);
            F32X2_PACK(nbz2, nbz, nbz);
            float best = 0.0f; int besti = 0x7fffffff;
#pragma unroll
            for (int a = 0; a < NP2; a++) {
                unsigned long long dx2, dy2, dz2, t2;
                F32X2_ADD(dx2, px2[a], nbx2);           // lx - bx (IEEE-identical to sub)
                F32X2_ADD(dy2, py2[a], nby2);
                F32X2_ADD(dz2, pz2[a], nbz2);
                F32X2_MUL(t2, dz2, dz2);                // dz*dz
                F32X2_FMA(t2, dy2, dy2, t2);            // dy*dy + .
                F32X2_FMA(t2, dx2, dx2, t2);            // dx*dx + .  (== R4 fmaf chain)
                float d0, d1;
                F32X2_UNPACK(d0, d1, t2);
                float v0 = fminf(md[2*a], d0);   md[2*a]   = v0;
                float v1 = fminf(md[2*a+1], d1); md[2*a+1] = v1;
                int g0 = (2*a)   * T + tid;
                int g1 = (2*a+1) * T + tid;
                if (v0 > best || (v0 == best && g0 < besti)) { best = v0; besti = g0; }
                if (v1 > best || (v1 == best && g1 < besti)) { best = v1; besti = g1; }
            }
            // warp argmax via REDUX (dists >= 0 so float bits are order-preserving)
            unsigned bb = __float_as_uint(best);
            unsigned mb = __reduce_max_sync(0xffffffffu, bb);
            int cand = (bb == mb) ? besti : 0x7fffffff;
            int wbi = __reduce_min_sync(0xffffffffu, cand);
            if ((tid & 31) == 0)
                atomicMax(&s_key[t & 3],
                          ((unsigned long long)mb << 32) | (unsigned)(0x7fffffff - wbi));
            __syncthreads();
            unsigned long long key = s_key[t & 3];
            int win = 0x7fffffff - (int)(unsigned)(key & 0xffffffffu);
            const float* wp = pb + (size_t)win * 3;     // uniform address, L1-hot
            bx = wp[0]; by = wp[1]; bz = wp[2];
            if (tid == 0) {
                float* o = newp + ((size_t)b * M + t) * 3;
                o[0] = bx; o[1] = by; o[2] = bz;
            }
        }
    } else {
        // scalar path (NPT == 1): same single-barrier structure
        float lx = pb[tid*3+0], ly = pb[tid*3+1], lz = pb[tid*3+2], md = INFINITY;
        for (int t = 1; t < M; t++) {
            if (tid == 0) s_key[(t+2) & 3] = 0ull;
            float dx = lx-bx, dy = ly-by, dz = lz-bz;
            float d = fmaf(dx, dx, fmaf(dy, dy, dz*dz));
            float v = fminf(md, d);
            md = v;
            float best = v; int besti = tid;
            unsigned bb = __float_as_uint(best);
            unsigned mb = __reduce_max_sync(0xffffffffu, bb);
            int cand = (bb == mb) ? besti : 0x7fffffff;
            int wbi = __reduce_min_sync(0xffffffffu, cand);
            if ((tid & 31) == 0)
                atomicMax(&s_key[t & 3],
                          ((unsigned long long)mb << 32) | (unsigned)(0x7fffffff - wbi));
            __syncthreads();
            unsigned long long key = s_key[t & 3];
            int win = 0x7fffffff - (int)(unsigned)(key & 0xffffffffu);
            const float* wp = pb + (size_t)win * 3;
            bx = wp[0]; by = wp[1]; bz = wp[2];
            if (tid == 0) {
                float* o = newp + ((size_t)b * M + t) * 3;
                o[0] = bx; o[1] = by; o[2] = bz;
            }
        }
    }
}

// ---------------- kNN (R12-proven): 128 thr, packed init, cached minima, owner rescan ----------------
__global__ void knn_kernel(const float* __restrict__ p, const float* __restrict__ newp,
                           int N, int M, int* __restrict__ knn) {
    extern __shared__ float dist[];          // N floats
    __shared__ float s_tmin[128];
    __shared__ int   s_tidx[128];
    __shared__ int   s_win;
    const int q = blockIdx.x;
    const int b = q / M;
    const int tid = threadIdx.x;
    const float* pb = p + (size_t)b * N * 3;
    const float qx = newp[q*3+0], qy = newp[q*3+1], qz = newp[q*3+2];
    float bd = INFINITY; int bi = 0x7fffffff;
    {
        float nqx = -qx, nqy = -qy, nqz = -qz;
        unsigned long long nqx2, nqy2, nqz2;
        F32X2_PACK(nqx2, nqx, nqx);
        F32X2_PACK(nqy2, nqy, nqy);
        F32X2_PACK(nqz2, nqz, nqz);
        int n = tid;
        for (; n + 128 < N; n += 256) {
            int n1 = n + 128;
            unsigned long long px2, py2, pz2, dx2, dy2, dz2, t2;
            F32X2_PACK(px2, pb[n*3+0], pb[n1*3+0]);
            F32X2_PACK(py2, pb[n*3+1], pb[n1*3+1]);
            F32X2_PACK(pz2, pb[n*3+2], pb[n1*3+2]);
            F32X2_ADD(dx2, px2, nqx2);       // p - q
            F32X2_ADD(dy2, py2, nqy2);
            F32X2_ADD(dz2, pz2, nqz2);
            F32X2_MUL(t2, dz2, dz2);
            F32X2_FMA(t2, dy2, dy2, t2);
            F32X2_FMA(t2, dx2, dx2, t2);     // == fmaf(dx,dx,fmaf(dy,dy,dz*dz))
            float d0, d1;
            F32X2_UNPACK(d0, d1, t2);
            dist[n]  = d0;
            dist[n1] = d1;
            if (d0 < bd) { bd = d0; bi = n;  }   // ascending n -> first-index ties
            if (d1 < bd) { bd = d1; bi = n1; }
        }
        for (; n < N; n += 128) {            // scalar tail (N < 256 stages)
            float dx = qx - pb[n*3+0], dy = qy - pb[n*3+1], dz = qz - pb[n*3+2];
            float d = fmaf(dx, dx, fmaf(dy, dy, dz*dz));
            dist[n] = d;
            if (d < bd) { bd = d; bi = n; }
        }
    }
    s_tmin[tid] = bd; s_tidx[tid] = bi;
    __syncthreads();
    for (int r = 0; ; r++) {
        if (tid < 32) {
            float m0 = s_tmin[tid]; int i0 = s_tidx[tid];
#pragma unroll
            for (int off = 32; off < 128; off += 32) {
                float mm = s_tmin[tid + off]; int ii = s_tidx[tid + off];
                if (mm < m0 || (mm == m0 && ii < i0)) { m0 = mm; i0 = ii; }
            }
            unsigned b0 = __float_as_uint(m0);
            unsigned mb = __reduce_min_sync(0xffffffffu, b0);
            int cand = (b0 == mb) ? i0 : 0x7fffffff;
            int win = __reduce_min_sync(0xffffffffu, cand);
            if (tid == 0) { knn[(size_t)q*16 + r] = win; s_win = win; }
        }
        __syncthreads();
        if (r == 15) break;
        int win = s_win;
        if ((win & 127) == tid) {            // owner rescans its slice
            dist[win] = INFINITY;
            float nb = INFINITY; int ni = 0x7fffffff;
            for (int n = tid; n < N; n += 128) {
                float d = dist[n];
                if (d < nb) { nb = d; ni = n; }
            }
            s_tmin[tid] = nb; s_tidx[tid] = ni;
        }
        __syncthreads();
    }
}

// ---------------- fused grouped GEMM + max/min over k + per-block channel stats ----------------
__global__ void td_gemm_fused(const float* __restrict__ p, const float* __restrict__ h,
                              const float* __restrict__ newp, const int* __restrict__ knn,
                              const float* __restrict__ W, int N, int M, int C, int D,
                              float* __restrict__ ymax, float* __restrict__ ymin,
                              float* __restrict__ part) {
    extern __shared__ float feat[];          // 16*(C+3)
    __shared__ int   s_knn[16];
    __shared__ float s_np[3];
    const int q = blockIdx.x;
    const int b = q / M;
    const int t = threadIdx.x;               // D threads, one per output channel
    if (t < 16) s_knn[t] = knn[(size_t)q*16 + t];
    if (t < 3)  s_np[t]  = newp[q*3 + t];
    __syncthreads();
    const int F = C + 3;
    const float* pb = p + (size_t)b * N * 3;
    const float* hb = h + (size_t)b * N * C;
    for (int e = t; e < 16 * F; e += D) {
        int k = e / F, c = e - k * F;
        int n = s_knn[k];
        feat[e] = (c < 3) ? (pb[n*3 + c] - s_np[c]) : hb[(size_t)n * C + (c - 3)];
    }
    __syncthreads();
    float acc[16];
#pragma unroll
    for (int k = 0; k < 16; k++) acc[k] = 0.f;
#pragma unroll 2
    for (int c = 0; c < F; c++) {
        float w = W[(size_t)c * D + t];      // loaded once per c
#pragma unroll
        for (int k = 0; k < 16; k++) acc[k] += feat[k*F + c] * w;   // LDS broadcast
    }
    float mx = -INFINITY, mn = INFINITY, s = 0.f, s2 = 0.f;
#pragma unroll
    for (int k = 0; k < 16; k++) {
        float v = acc[k];
        mx = fmaxf(mx, v); mn = fminf(mn, v);
        s += v; s2 += v * v;
    }
    ymax[(size_t)q * D + t] = mx;
    ymin[(size_t)q * D + t] = mn;
    part[(size_t)q * 2 * D + t]     = s;
    part[(size_t)q * 2 * D + D + t] = s2;
}

// ---------------- stats tree: level-1 reduce of per-block partials ----------------
__global__ void stats_reduce(const float* __restrict__ part, int Q, int D,
                             float* __restrict__ out) {
    const int t = threadIdx.x;               // D threads
    const int per = (Q + gridDim.x - 1) / gridDim.x;
    const int r0 = blockIdx.x * per;
    const int r1 = min(r0 + per, Q);
    float s = 0.f, s2 = 0.f;
    for (int r = r0; r < r1; r++) {
        s  += part[(size_t)r * 2 * D + t];
        s2 += part[(size_t)r * 2 * D + D + t];
    }
    out[(size_t)blockIdx.x * 2 * D + t]     = s;
    out[(size_t)blockIdx.x * 2 * D + D + t] = s2;
}

__global__ void stats_final(const float* __restrict__ part, int NB, int D, float cnt,
                            const float* __restrict__ g, const float* __restrict__ bta,
                            float* __restrict__ scale, float* __restrict__ shift) {
    const int c = threadIdx.x;
    if (c >= D) return;
    float S = 0.f, Q2 = 0.f;
    for (int i = 0; i < NB; i++) {
        S  += part[(size_t)i * 2 * D + c];
        Q2 += part[(size_t)i * 2 * D + D + c];
    }
    float m = S / cnt;
    float v = Q2 / cnt - m * m;
    float sc = g[c] * rsqrtf(v + BN_EPS);
    scale[c] = sc;
    shift[c] = bta[c] - m * sc;
}

// ---------------- apply BN+ReLU to the sign-appropriate extremum ----------------
__global__ void td_norm(const float* __restrict__ ymax, const float* __restrict__ ymin,
                        const float* __restrict__ scale, const float* __restrict__ shift,
                        int total, int D, float* __restrict__ hout) {
    int i = blockIdx.x * 256 + threadIdx.x;
    if (i >= total) return;
    int d = i % D;
    float sc = scale[d];
    float v = (sc >= 0.f) ? ymax[i] : ymin[i];
    hout[i] = fmaxf(0.f, sc * v + shift[d]);
}

// ---------------- stage 0: h = p @ W1 (3->32) ----------------
__global__ void s0_gemm(const float* __restrict__ x, const float* __restrict__ W1,
                        float* __restrict__ y) {
    int i = blockIdx.x * 256 + threadIdx.x;
    if (i >= 16*4096*32) return;
    int pt = i >> 5, c = i & 31;
    const float* xp = x + (size_t)pt * 3;
    y[i] = xp[0]*W1[c] + xp[1]*W1[32+c] + xp[2]*W1[64+c];
}

__global__ void stats_partial(const float* __restrict__ y, int Q, int D, float* __restrict__ part) {
    const int NB = gridDim.x;
    const int rpb = (Q + NB - 1) / NB;
    const int r0 = blockIdx.x * rpb;
    const int r1 = min(r0 + rpb, Q);
    __shared__ float ss[256], sq[256];
    const int tid = threadIdx.x;
    const int rpi = 256 / D;
    const int c = tid % D;
    const int ro = tid / D;
    float s = 0.f, q2 = 0.f;
    for (int r = r0 + ro; r < r1; r += rpi) {
        float v = y[(size_t)r * D + c]; s += v; q2 += v * v;
    }
    ss[tid] = s; sq[tid] = q2;
    __syncthreads();
    if (tid < D) {
        for (int o = 1; o < rpi; o++) { s += ss[tid + o*D]; q2 += sq[tid + o*D]; }
        part[(size_t)blockIdx.x * 2 * D + tid]     = s;
        part[(size_t)blockIdx.x * 2 * D + D + tid] = q2;
    }
}

__global__ void normalize_kernel(const float* __restrict__ y, const float* __restrict__ scale,
                                 const float* __restrict__ shift, int total, int D,
                                 float* __restrict__ out) {
    int i = blockIdx.x * 256 + threadIdx.x;
    if (i >= total) return;
    int c = i % D;
    out[i] = fmaxf(0.f, y[i] * scale[c] + shift[c]);
}

// ---------------- classifier head: single block, channel-per-thread ----------------
__global__ void classifier_kernel(const float* __restrict__ h4,
                                  const float* __restrict__ Wc1, const float* __restrict__ bc1,
                                  const float* __restrict__ gc1, const float* __restrict__ hc1,
                                  const float* __restrict__ Wc2, const float* __restrict__ bc2,
                                  const float* __restrict__ gc2, const float* __restrict__ hc2,
                                  const float* __restrict__ Wc3, const float* __restrict__ bc3,
                                  float* __restrict__ out) {
    __shared__ float sb[12288];
    float* z  = sb;
    float* z1 = sb + 8192;
    const int t = threadIdx.x;  // 256 threads
    for (int e = t; e < 8192; e += 256) {
        int b = e >> 9, c = e & 511;
        float s = 0.f;
        for (int k = 0; k < 16; k++) s += h4[((size_t)(b*16 + k))*512 + c];
        z[e] = s * (1.f/16.f);
    }
    __syncthreads();
    {
        float acc[16];
#pragma unroll
        for (int b = 0; b < 16; b++) acc[b] = bc1[t];
        for (int i = 0; i < 512; i++) {
            float w = Wc1[(size_t)i*256 + t];
#pragma unroll
            for (int b = 0; b < 16; b++) acc[b] += z[b*512 + i] * w;
        }
        float m = 0.f;
#pragma unroll
        for (int b = 0; b < 16; b++) m += acc[b];
        m *= (1.f/16.f);
        float v = 0.f;
#pragma unroll
        for (int b = 0; b < 16; b++) { float d = acc[b]-m; v += d*d; }
        v *= (1.f/16.f);
        float sc = gc1[t] * rsqrtf(v + BN_EPS);
        float sh = hc1[t] - m * sc;
#pragma unroll
        for (int b = 0; b < 16; b++) z1[b*256 + t] = fmaxf(0.f, acc[b]*sc + sh);
    }
    __syncthreads();
    float* z2 = sb;
    if (t < 128) {
        float acc[16];
#pragma unroll
        for (int b = 0; b < 16; b++) acc[b] = bc2[t];
        for (int i = 0; i < 256; i++) {
            float w = Wc2[(size_t)i*128 + t];
#pragma unroll
            for (int b = 0; b < 16; b++) acc[b] += z1[b*256 + i] * w;
        }
        float m = 0.f;
#pragma unroll
        for (int b = 0; b < 16; b++) m += acc[b];
        m *= (1.f/16.f);
        float v = 0.f;
#pragma unroll
        for (int b = 0; b < 16; b++) { float d = acc[b]-m; v += d*d; }
        v *= (1.f/16.f);
        float sc = gc2[t] * rsqrtf(v + BN_EPS);
        float sh = hc2[t] - m * sc;
#pragma unroll
        for (int b = 0; b < 16; b++) z2[b*128 + t] = fmaxf(0.f, acc[b]*sc + sh);
    }
    __syncthreads();
    if (t < 40) {
        float acc[16];
#pragma unroll
        for (int b = 0; b < 16; b++) acc[b] = bc3[t];
        for (int i = 0; i < 128; i++) {
            float w = Wc3[(size_t)i*40 + t];
#pragma unroll
            for (int b = 0; b < 16; b++) acc[b] += z2[b*128 + i] * w;
        }
#pragma unroll
        for (int b = 0; b < 16; b++) out[b*40 + t] = acc[b];
    }
}

// ---------------- driver ----------------
extern "C" void kernel_launch(void* const* d_in, const int* in_sizes, int n_in,
                              void* d_out, int out_size) {
    (void)in_sizes; (void)n_in; (void)out_size;
    const float* x   = (const float*)d_in[0];
    const float* W1  = (const float*)d_in[1];
    const float* g1  = (const float*)d_in[2];
    const float* b1  = (const float*)d_in[3];
    const float* W2  = (const float*)d_in[4];
    const float* g2  = (const float*)d_in[5];
    const float* b2  = (const float*)d_in[6];
    const float* W3  = (const float*)d_in[7];
    const float* g3  = (const float*)d_in[8];
    const float* b3  = (const float*)d_in[9];
    const float* W4  = (const float*)d_in[10];
    const float* g4  = (const float*)d_in[11];
    const float* b4  = (const float*)d_in[12];
    const float* W5  = (const float*)d_in[13];
    const float* g5  = (const float*)d_in[14];
    const float* b5  = (const float*)d_in[15];
    const float* Wc1 = (const float*)d_in[16];
    const float* bc1 = (const float*)d_in[17];
    const float* gc1 = (const float*)d_in[18];
    const float* hc1 = (const float*)d_in[19];
    const float* Wc2 = (const float*)d_in[20];
    const float* bc2 = (const float*)d_in[21];
    const float* gc2 = (const float*)d_in[22];
    const float* hc2 = (const float*)d_in[23];
    const float* Wc3 = (const float*)d_in[24];
    const float* bc3 = (const float*)d_in[25];
    float* out = (float*)d_out;

    float *ybuf, *h0, *p1, *h1, *p2, *h2, *p3, *h3, *p4, *h4, *part0, *scale, *shift;
    int* knn;
    cudaGetSymbolAddress((void**)&ybuf,  g_ybuf);
    cudaGetSymbolAddress((void**)&h0,    g_h0);
    cudaGetSymbolAddress((void**)&p1,    g_p1);
    cudaGetSymbolAddress((void**)&h1,    g_h1);
    cudaGetSymbolAddress((void**)&p2,    g_p2);
    cudaGetSymbolAddress((void**)&h2,    g_h2);
    cudaGetSymbolAddress((void**)&p3,    g_p3);
    cudaGetSymbolAddress((void**)&h3,    g_h3);
    cudaGetSymbolAddress((void**)&p4,    g_p4);
    cudaGetSymbolAddress((void**)&h4,    g_h4);
    cudaGetSymbolAddress((void**)&knn,   g_knn);
    cudaGetSymbolAddress((void**)&part0, g_part);
    cudaGetSymbolAddress((void**)&scale, g_scale);
    cudaGetSymbolAddress((void**)&shift, g_shift);

    // carve scratch from ybuf (temporally disjoint with stage0's use of ybuf[0..2M))
    float* ymax  = ybuf;                       // <= 1,048,576 floats
    float* ymin  = ybuf + 1048576;
    float* part  = ybuf + 2097152;             // <= 2,097,152 floats (TD1)
    float* part2 = ybuf + 4194304;             // <= 65,536 floats
    const int NR = 64;

    const bool ov = g_sync.ok;
    cudaStream_t SB = ov ? g_sync.sb : 0;

    // ---- fork: FPS chain on side stream (positions only; independent of features) ----
    if (ov) { cudaEventRecord(g_sync.fork, 0); cudaStreamWaitEvent(SB, g_sync.fork, 0); }
    fps_kernel<4096, 512><<<16, 512, 0, SB>>>(x, 1024, p1);
    if (ov) cudaEventRecord(g_sync.e1, SB);
    fps_kernel<1024, 256><<<16, 256, 0, SB>>>(p1, 256, p2);
    if (ov) cudaEventRecord(g_sync.e2, SB);
    fps_kernel<256, 256><<<16, 256, 0, SB>>>(p2, 64, p3);
    if (ov) cudaEventRecord(g_sync.e3, SB);
    fps_kernel<64, 64><<<16, 64, 0, SB>>>(p3, 16, p4);
    if (ov) cudaEventRecord(g_sync.e4, SB);

    // ---- main stream: stage 0 (overlaps fps1) ----
    s0_gemm<<<(16*4096*32 + 255)/256, 256>>>(x, W1, ybuf);
    stats_partial<<<512, 256>>>(ybuf, 16*4096, 32, part0);
    stats_final<<<1, 32>>>(part0, 512, 32, (float)(16*4096), g1, b1, scale, shift);
    normalize_kernel<<<(16*4096*32 + 255)/256, 256>>>(ybuf, scale, shift, 16*4096*32, 32, h0);

    // ---- TD1: 4096 -> 1024, C=32 -> D=64 ----
    if (ov) cudaStreamWaitEvent(0, g_sync.e1, 0);
    knn_kernel<<<16*1024, 128, 4096*4>>>(x, p1, 4096, 1024, knn);
    td_gemm_fused<<<16*1024, 64, 16*35*4>>>(x, h0, p1, knn, W2, 4096, 1024, 32, 64, ymax, ymin, part);
    stats_reduce<<<NR, 64>>>(part, 16*1024, 64, part2);
    stats_final<<<1, 64>>>(part2, NR, 64, (float)(16*1024*16), g2, b2, scale, shift);
    td_norm<<<(16*1024*64 + 255)/256, 256>>>(ymax, ymin, scale, shift, 16*1024*64, 64, h1);

    // ---- TD2: 1024 -> 256, C=64 -> D=128 ----
    if (ov) cudaStreamWaitEvent(0, g_sync.e2, 0);
    knn_kernel<<<16*256, 128, 1024*4>>>(p1, p2, 1024, 256, knn);
    td_gemm_fused<<<16*256, 128, 16*67*4>>>(p1, h1, p2, knn, W3, 1024, 256, 64, 128, ymax, ymin, part);
    stats_reduce<<<NR, 128>>>(part, 16*256, 128, part2);
    stats_final<<<1, 128>>>(part2, NR, 128, (float)(16*256*16), g3, b3, scale, shift);
    td_norm<<<(16*256*128 + 255)/256, 256>>>(ymax, ymin, scale, shift, 16*256*128, 128, h2);

    // ---- TD3: 256 -> 64, C=128 -> D=256 ----
    if (ov) cudaStreamWaitEvent(0, g_sync.e3, 0);
    knn_kernel<<<16*64, 128, 256*4>>>(p2, p3, 256, 64, knn);
    td_gemm_fused<<<16*64, 256, 16*131*4>>>(p2, h2, p3, knn, W4, 256, 64, 128, 256, ymax, ymin, part);
    stats_reduce<<<NR, 256>>>(part, 16*64, 256, part2);
    stats_final<<<1, 256>>>(part2, NR, 256, (float)(16*64*16), g4, b4, scale, shift);
    td_norm<<<(16*64*256 + 255)/256, 256>>>(ymax, ymin, scale, shift, 16*64*256, 256, h3);

    // ---- TD4: 64 -> 16, C=256 -> D=512 (join: waits last side-stream event) ----
    if (ov) cudaStreamWaitEvent(0, g_sync.e4, 0);
    knn_kernel<<<16*16, 128, 64*4>>>(p3, p4, 64, 16, knn);
    td_gemm_fused<<<16*16, 512, 16*259*4>>>(p3, h3, p4, knn, W5, 64, 16, 256, 512, ymax, ymin, part);
    stats_reduce<<<NR, 512>>>(part, 16*16, 512, part2);
    stats_final<<<1, 512>>>(part2, NR, 512, (float)(16*16*16), g5, b5, scale, shift);
    td_norm<<<(16*16*512 + 255)/256, 256>>>(ymax, ymin, scale, shift, 16*16*512, 512, h4);

    // ---- classifier head ----
    classifier_kernel<<<1, 256>>>(h4, Wc1, bc1, gc1, hc1, Wc2, bc2, gc2, hc2, Wc3, bc3, out);
}

// round 15
// speedup vs baseline: 2.0182x; 1.1198x over previous
#include <cuda_runtime.h>
#include <math.h>

#define BN_EPS 1e-5f

// packed f32x2 helpers (sm_100+; only reachable via PTX; add/mul/fma only)
#define F32X2_PACK(o, lo, hi)  asm("mov.b64 %0, {%1, %2};" : "=l"(o) : "f"(lo), "f"(hi))
#define F32X2_UNPACK(lo, hi, i) asm("mov.b64 {%0, %1}, %2;" : "=f"(lo), "=f"(hi) : "l"(i))
#define F32X2_ADD(o, a, b)     asm("add.rn.f32x2 %0, %1, %2;" : "=l"(o) : "l"(a), "l"(b))
#define F32X2_MUL(o, a, b)     asm("mul.rn.f32x2 %0, %1, %2;" : "=l"(o) : "l"(a), "l"(b))
#define F32X2_FMA(o, a, b, c)  asm("fma.rn.f32x2 %0, %1, %2, %3;" : "=l"(o) : "l"(a), "l"(b), "l"(c))

// ---------------- scratch (static device globals; no allocations) ----------------
__device__ float g_ybuf[16*1024*16*64];   // carved: stage0 ybuf | ymax | ymin | part | part2
__device__ float g_h0[16*4096*32];
__device__ float g_p1[16*1024*3];
__device__ float g_h1[16*1024*64];
__device__ float g_p2[16*256*3];
__device__ float g_h2[16*256*128];
__device__ float g_p3[16*64*3];
__device__ float g_h3[16*64*256];
__device__ float g_p4[16*16*3];
__device__ float g_h4[16*16*512];
__device__ int   g_knn[16*1024*16];
__device__ float g_part[512*2*512];       // stage0 partials [NB][2][D]
__device__ float g_scale[512];
__device__ float g_shift[512];
__device__ float g_md[16*4096];           // fps1 inter-segment min-dist carry

// ---------------- side stream + fork/join events (created at load, before checkpoints) ----------------
struct GpuSync {
    cudaStream_t sb = nullptr;
    cudaEvent_t fork = nullptr, ea = nullptr, eb = nullptr, ec = nullptr,
                e1 = nullptr, e2 = nullptr, e3 = nullptr, e4 = nullptr;
    bool ok = false;
    GpuSync() {
        ok = (cudaStreamCreateWithFlags(&sb, cudaStreamNonBlocking) == cudaSuccess)
          && (cudaEventCreateWithFlags(&fork, cudaEventDisableTiming) == cudaSuccess)
          && (cudaEventCreateWithFlags(&ea,   cudaEventDisableTiming) == cudaSuccess)
          && (cudaEventCreateWithFlags(&eb,   cudaEventDisableTiming) == cudaSuccess)
          && (cudaEventCreateWithFlags(&ec,   cudaEventDisableTiming) == cudaSuccess)
          && (cudaEventCreateWithFlags(&e1,   cudaEventDisableTiming) == cudaSuccess)
          && (cudaEventCreateWithFlags(&e2,   cudaEventDisableTiming) == cudaSuccess)
          && (cudaEventCreateWithFlags(&e3,   cudaEventDisableTiming) == cudaSuccess)
          && (cudaEventCreateWithFlags(&e4,   cudaEventDisableTiming) == cudaSuccess);
    }
};
static GpuSync g_sync;

// ---------------- FPS (R12-proven step structure), segmentable over [t0, t1) ----------------
// Segments carry md[] via mdbuf (bit-exact continuation). t0==0: init; t1==M: no save.
template<int N, int T>
__global__ void fps_kernel(const float* __restrict__ p, int M, float* __restrict__ newp,
                           int t0, int t1, float* __restrict__ mdbuf) {
    constexpr int NPT = N / T;
    constexpr int NW  = T / 32;
    const int b = blockIdx.x, tid = threadIdx.x;
    const float* pb = p + (size_t)b * N * 3;
    __shared__ unsigned s_wd[16];
    __shared__ int      s_wi[16];
    __shared__ float    s_b[3];
    float bx, by, bz;
    int start;
    if (t0 == 0) {
        if (tid == 0) {
            float* o = newp + (size_t)b * M * 3;
            o[0] = pb[0]; o[1] = pb[1]; o[2] = pb[2];
        }
        bx = pb[0]; by = pb[1]; bz = pb[2];
        start = 1;
    } else {
        const float* pr = newp + ((size_t)b * M + (t0 - 1)) * 3;  // last selected row
        bx = pr[0]; by = pr[1]; bz = pr[2];
        start = t0;
    }

    if constexpr (NPT >= 2) {
        constexpr int NP2 = NPT / 2;
        unsigned long long px2[NP2], py2[NP2], pz2[NP2];
        float md[NPT];
#pragma unroll
        for (int a = 0; a < NP2; a++) {
            int g0 = (2*a)   * T + tid;
            int g1 = (2*a+1) * T + tid;
            F32X2_PACK(px2[a], pb[g0*3+0], pb[g1*3+0]);
            F32X2_PACK(py2[a], pb[g0*3+1], pb[g1*3+1]);
            F32X2_PACK(pz2[a], pb[g0*3+2], pb[g1*3+2]);
        }
        if (t0 == 0) {
#pragma unroll
            for (int j = 0; j < NPT; j++) md[j] = INFINITY;
        } else {
#pragma unroll
            for (int j = 0; j < NPT; j++) md[j] = mdbuf[(size_t)b * N + j * T + tid];
        }
        for (int t = start; t < t1; t++) {
            float nbx = -bx, nby = -by, nbz = -bz;
            unsigned long long nbx2, nby2, nbz2;
            F32X2_PACK(nbx2, nbx, nbx);
            F32X2_PACK(nby2, nby, nby);
            F32X2_PACK(nbz2, nbz, nbz);
            float best = 0.0f; int besti = 0x7fffffff;
#pragma unroll
            for (int a = 0; a < NP2; a++) {
                unsigned long long dx2, dy2, dz2, t2;
                F32X2_ADD(dx2, px2[a], nbx2);           // lx - bx (IEEE-identical to sub)
                F32X2_ADD(dy2, py2[a], nby2);
                F32X2_ADD(dz2, pz2[a], nbz2);
                F32X2_MUL(t2, dz2, dz2);                // dz*dz
                F32X2_FMA(t2, dy2, dy2, t2);            // dy*dy + .
                F32X2_FMA(t2, dx2, dx2, t2);            // dx*dx + .  (== R4 fmaf chain)
                float d0, d1;
                F32X2_UNPACK(d0, d1, t2);
                float v0 = fminf(md[2*a], d0);   md[2*a]   = v0;
                float v1 = fminf(md[2*a+1], d1); md[2*a+1] = v1;
                int g0 = (2*a)   * T + tid;
                int g1 = (2*a+1) * T + tid;
                if (v0 > best || (v0 == best && g0 < besti)) { best = v0; besti = g0; }
                if (v1 > best || (v1 == best && g1 < besti)) { best = v1; besti = g1; }
            }
            // warp argmax via REDUX (dists >= 0 so float bits are order-preserving)
            unsigned bb = __float_as_uint(best);
            unsigned mb = __reduce_max_sync(0xffffffffu, bb);
            int cand = (bb == mb) ? besti : 0x7fffffff;
            int wbi = __reduce_min_sync(0xffffffffu, cand);
            if ((tid & 31) == 0) { s_wd[tid >> 5] = mb; s_wi[tid >> 5] = wbi; }
            __syncthreads();
            if (tid < 32) {
                unsigned u = (tid < NW) ? s_wd[tid] : 0u;
                int      ii = (tid < NW) ? s_wi[tid] : 0x7fffffff;
                unsigned m2 = __reduce_max_sync(0xffffffffu, u);
                int c2 = (u == m2) ? ii : 0x7fffffff;
                int win = __reduce_min_sync(0xffffffffu, c2);
                if (tid == 0) {
                    const float* wp = pb + (size_t)win * 3;   // L1-hot
                    float cx = wp[0], cy = wp[1], cz = wp[2];
                    s_b[0] = cx; s_b[1] = cy; s_b[2] = cz;
                    float* o = newp + ((size_t)b * M + t) * 3;
                    o[0] = cx; o[1] = cy; o[2] = cz;
                }
            }
            __syncthreads();
            bx = s_b[0]; by = s_b[1]; bz = s_b[2];
        }
        if (t1 < M) {
#pragma unroll
            for (int j = 0; j < NPT; j++) mdbuf[(size_t)b * N + j * T + tid] = md[j];
        }
    } else {
        // scalar path (NPT == 1): full-range only (fps4)
        float lx = pb[tid*3+0], ly = pb[tid*3+1], lz = pb[tid*3+2], md = INFINITY;
        for (int t = 1; t < M; t++) {
            float best = 0.0f; int besti = 0x7fffffff;
            float dx = lx-bx, dy = ly-by, dz = lz-bz;
            float d = fmaf(dx, dx, fmaf(dy, dy, dz*dz));
            float v = fminf(md, d);
            md = v;
            if (v > best || (v == best && tid < besti)) { best = v; besti = tid; }
            unsigned bb = __float_as_uint(best);
            unsigned mb = __reduce_max_sync(0xffffffffu, bb);
            int cand = (bb == mb) ? besti : 0x7fffffff;
            int wbi = __reduce_min_sync(0xffffffffu, cand);
            if ((tid & 31) == 0) { s_wd[tid >> 5] = mb; s_wi[tid >> 5] = wbi; }
            __syncthreads();
            if (tid < 32) {
                unsigned u = (tid < NW) ? s_wd[tid] : 0u;
                int      ii = (tid < NW) ? s_wi[tid] : 0x7fffffff;
                unsigned m2 = __reduce_max_sync(0xffffffffu, u);
                int c2 = (u == m2) ? ii : 0x7fffffff;
                int win = __reduce_min_sync(0xffffffffu, c2);
                if (tid == 0) {
                    const float* wp = pb + (size_t)win * 3;
                    float cx = wp[0], cy = wp[1], cz = wp[2];
                    s_b[0] = cx; s_b[1] = cy; s_b[2] = cz;
                    float* o = newp + ((size_t)b * M + t) * 3;
                    o[0] = cx; o[1] = cy; o[2] = cz;
                }
            }
            __syncthreads();
            bx = s_b[0]; by = s_b[1]; bz = s_b[2];
        }
    }
}

// ---------------- kNN (R12-proven), chunked over query rows [q0, q0+qcnt) per batch ----------------
__global__ void knn_kernel(const float* __restrict__ p, const float* __restrict__ newp,
                           int N, int M, int* __restrict__ knn, int q0, int qcnt) {
    extern __shared__ float dist[];          // N floats
    __shared__ float s_tmin[128];
    __shared__ int   s_tidx[128];
    __shared__ int   s_win;
    const int b = blockIdx.x / qcnt;
    const int q = b * M + q0 + (blockIdx.x - b * qcnt);
    const int tid = threadIdx.x;
    const float* pb = p + (size_t)b * N * 3;
    const float qx = newp[q*3+0], qy = newp[q*3+1], qz = newp[q*3+2];
    float bd = INFINITY; int bi = 0x7fffffff;
    {
        float nqx = -qx, nqy = -qy, nqz = -qz;
        unsigned long long nqx2, nqy2, nqz2;
        F32X2_PACK(nqx2, nqx, nqx);
        F32X2_PACK(nqy2, nqy, nqy);
        F32X2_PACK(nqz2, nqz, nqz);
        int n = tid;
        for (; n + 128 < N; n += 256) {
            int n1 = n + 128;
            unsigned long long px2, py2, pz2, dx2, dy2, dz2, t2;
            F32X2_PACK(px2, pb[n*3+0], pb[n1*3+0]);
            F32X2_PACK(py2, pb[n*3+1], pb[n1*3+1]);
            F32X2_PACK(pz2, pb[n*3+2], pb[n1*3+2]);
            F32X2_ADD(dx2, px2, nqx2);       // p - q
            F32X2_ADD(dy2, py2, nqy2);
            F32X2_ADD(dz2, pz2, nqz2);
            F32X2_MUL(t2, dz2, dz2);
            F32X2_FMA(t2, dy2, dy2, t2);
            F32X2_FMA(t2, dx2, dx2, t2);     // == fmaf(dx,dx,fmaf(dy,dy,dz*dz))
            float d0, d1;
            F32X2_UNPACK(d0, d1, t2);
            dist[n]  = d0;
            dist[n1] = d1;
            if (d0 < bd) { bd = d0; bi = n;  }   // ascending n -> first-index ties
            if (d1 < bd) { bd = d1; bi = n1; }
        }
        for (; n < N; n += 128) {            // scalar tail (N < 256 stages)
            float dx = qx - pb[n*3+0], dy = qy - pb[n*3+1], dz = qz - pb[n*3+2];
            float d = fmaf(dx, dx, fmaf(dy, dy, dz*dz));
            dist[n] = d;
            if (d < bd) { bd = d; bi = n; }
        }
    }
    s_tmin[tid] = bd; s_tidx[tid] = bi;
    __syncthreads();
    for (int r = 0; ; r++) {
        if (tid < 32) {
            float m0 = s_tmin[tid]; int i0 = s_tidx[tid];
#pragma unroll
            for (int off = 32; off < 128; off += 32) {
                float mm = s_tmin[tid + off]; int ii = s_tidx[tid + off];
                if (mm < m0 || (mm == m0 && ii < i0)) { m0 = mm; i0 = ii; }
            }
            unsigned b0 = __float_as_uint(m0);
            unsigned mb = __reduce_min_sync(0xffffffffu, b0);
            int cand = (b0 == mb) ? i0 : 0x7fffffff;
            int win = __reduce_min_sync(0xffffffffu, cand);
            if (tid == 0) { knn[(size_t)q*16 + r] = win; s_win = win; }
        }
        __syncthreads();
        if (r == 15) break;
        int win = s_win;
        if ((win & 127) == tid) {            // owner rescans its slice
            dist[win] = INFINITY;
            float nb = INFINITY; int ni = 0x7fffffff;
            for (int n = tid; n < N; n += 128) {
                float d = dist[n];
                if (d < nb) { nb = d; ni = n; }
            }
            s_tmin[tid] = nb; s_tidx[tid] = ni;
        }
        __syncthreads();
    }
}

// ------- fused grouped GEMM + max/min over k + per-block channel stats (chunked) -------
__global__ void td_gemm_fused(const float* __restrict__ p, const float* __restrict__ h,
                              const float* __restrict__ newp, const int* __restrict__ knn,
                              const float* __restrict__ W, int N, int M, int C, int D,
                              float* __restrict__ ymax, float* __restrict__ ymin,
                              float* __restrict__ part, int q0, int qcnt) {
    extern __shared__ float feat[];          // 16*(C+3)
    __shared__ int   s_knn[16];
    __shared__ float s_np[3];
    const int b = blockIdx.x / qcnt;
    const int q = b * M + q0 + (blockIdx.x - b * qcnt);
    const int t = threadIdx.x;               // D threads, one per output channel
    if (t < 16) s_knn[t] = knn[(size_t)q*16 + t];
    if (t < 3)  s_np[t]  = newp[q*3 + t];
    __syncthreads();
    const int F = C + 3;
    const float* pb = p + (size_t)b * N * 3;
    const float* hb = h + (size_t)b * N * C;
    for (int e = t; e < 16 * F; e += D) {
        int k = e / F, c = e - k * F;
        int n = s_knn[k];
        feat[e] = (c < 3) ? (pb[n*3 + c] - s_np[c]) : hb[(size_t)n * C + (c - 3)];
    }
    __syncthreads();
    float acc[16];
#pragma unroll
    for (int k = 0; k < 16; k++) acc[k] = 0.f;
#pragma unroll 2
    for (int c = 0; c < F; c++) {
        float w = W[(size_t)c * D + t];      // loaded once per c
#pragma unroll
        for (int k = 0; k < 16; k++) acc[k] += feat[k*F + c] * w;   // LDS broadcast
    }
    float mx = -INFINITY, mn = INFINITY, s = 0.f, s2 = 0.f;
#pragma unroll
    for (int k = 0; k < 16; k++) {
        float v = acc[k];
        mx = fmaxf(mx, v); mn = fminf(mn, v);
        s += v; s2 += v * v;
    }
    ymax[(size_t)q * D + t] = mx;
    ymin[(size_t)q * D + t] = mn;
    part[(size_t)q * 2 * D + t]     = s;
    part[(size_t)q * 2 * D + D + t] = s2;
}

// ---------------- stats tree: level-1 reduce of per-block partials ----------------
__global__ void stats_reduce(const float* __restrict__ part, int Q, int D,
                             float* __restrict__ out) {
    const int t = threadIdx.x;               // D threads
    const int per = (Q + gridDim.x - 1) / gridDim.x;
    const int r0 = blockIdx.x * per;
    const int r1 = min(r0 + per, Q);
    float s = 0.f, s2 = 0.f;
    for (int r = r0; r < r1; r++) {
        s  += part[(size_t)r * 2 * D + t];
        s2 += part[(size_t)r * 2 * D + D + t];
    }
    out[(size_t)blockIdx.x * 2 * D + t]     = s;
    out[(size_t)blockIdx.x * 2 * D + D + t] = s2;
}

__global__ void stats_final(const float* __restrict__ part, int NB, int D, float cnt,
                            const float* __restrict__ g, const float* __restrict__ bta,
                            float* __restrict__ scale, float* __restrict__ shift) {
    const int c = threadIdx.x;
    if (c >= D) return;
    float S = 0.f, Q2 = 0.f;
    for (int i = 0; i < NB; i++) {
        S  += part[(size_t)i * 2 * D + c];
        Q2 += part[(size_t)i * 2 * D + D + c];
    }
    float m = S / cnt;
    float v = Q2 / cnt - m * m;
    float sc = g[c] * rsqrtf(v + BN_EPS);
    scale[c] = sc;
    shift[c] = bta[c] - m * sc;
}

// ---------------- apply BN+ReLU to the sign-appropriate extremum ----------------
__global__ void td_norm(const float* __restrict__ ymax, const float* __restrict__ ymin,
                        const float* __restrict__ scale, const float* __restrict__ shift,
                        int total, int D, float* __restrict__ hout) {
    int i = blockIdx.x * 256 + threadIdx.x;
    if (i >= total) return;
    int d = i % D;
    float sc = scale[d];
    float v = (sc >= 0.f) ? ymax[i] : ymin[i];
    hout[i] = fmaxf(0.f, sc * v + shift[d]);
}

// ---------------- stage 0: h = p @ W1 (3->32) ----------------
__global__ void s0_gemm(const float* __restrict__ x, const float* __restrict__ W1,
                        float* __restrict__ y) {
    int i = blockIdx.x * 256 + threadIdx.x;
    if (i >= 16*4096*32) return;
    int pt = i >> 5, c = i & 31;
    const float* xp = x + (size_t)pt * 3;
    y[i] = xp[0]*W1[c] + xp[1]*W1[32+c] + xp[2]*W1[64+c];
}

__global__ void stats_partial(const float* __restrict__ y, int Q, int D, float* __restrict__ part) {
    const int NB = gridDim.x;
    const int rpb = (Q + NB - 1) / NB;
    const int r0 = blockIdx.x * rpb;
    const int r1 = min(r0 + rpb, Q);
    __shared__ float ss[256], sq[256];
    const int tid = threadIdx.x;
    const int rpi = 256 / D;
    const int c = tid % D;
    const int ro = tid / D;
    float s = 0.f, q2 = 0.f;
    for (int r = r0 + ro; r < r1; r += rpi) {
        float v = y[(size_t)r * D + c]; s += v; q2 += v * v;
    }
    ss[tid] = s; sq[tid] = q2;
    __syncthreads();
    if (tid < D) {
        for (int o = 1; o < rpi; o++) { s += ss[tid + o*D]; q2 += sq[tid + o*D]; }
        part[(size_t)blockIdx.x * 2 * D + tid]     = s;
        part[(size_t)blockIdx.x * 2 * D + D + tid] = q2;
    }
}

__global__ void normalize_kernel(const float* __restrict__ y, const float* __restrict__ scale,
                                 const float* __restrict__ shift, int total, int D,
                                 float* __restrict__ out) {
    int i = blockIdx.x * 256 + threadIdx.x;
    if (i >= total) return;
    int c = i % D;
    out[i] = fmaxf(0.f, y[i] * scale[c] + shift[c]);
}

// ---------------- classifier head: single block, channel-per-thread ----------------
__global__ void classifier_kernel(const float* __restrict__ h4,
                                  const float* __restrict__ Wc1, const float* __restrict__ bc1,
                                  const float* __restrict__ gc1, const float* __restrict__ hc1,
                                  const float* __restrict__ Wc2, const float* __restrict__ bc2,
                                  const float* __restrict__ gc2, const float* __restrict__ hc2,
                                  const float* __restrict__ Wc3, const float* __restrict__ bc3,
                                  float* __restrict__ out) {
    __shared__ float sb[12288];
    float* z  = sb;
    float* z1 = sb + 8192;
    const int t = threadIdx.x;  // 256 threads
    for (int e = t; e < 8192; e += 256) {
        int b = e >> 9, c = e & 511;
        float s = 0.f;
        for (int k = 0; k < 16; k++) s += h4[((size_t)(b*16 + k))*512 + c];
        z[e] = s * (1.f/16.f);
    }
    __syncthreads();
    {
        float acc[16];
#pragma unroll
        for (int b = 0; b < 16; b++) acc[b] = bc1[t];
        for (int i = 0; i < 512; i++) {
            float w = Wc1[(size_t)i*256 + t];
#pragma unroll
            for (int b = 0; b < 16; b++) acc[b] += z[b*512 + i] * w;
        }
        float m = 0.f;
#pragma unroll
        for (int b = 0; b < 16; b++) m += acc[b];
        m *= (1.f/16.f);
        float v = 0.f;
#pragma unroll
        for (int b = 0; b < 16; b++) { float d = acc[b]-m; v += d*d; }
        v *= (1.f/16.f);
        float sc = gc1[t] * rsqrtf(v + BN_EPS);
        float sh = hc1[t] - m * sc;
#pragma unroll
        for (int b = 0; b < 16; b++) z1[b*256 + t] = fmaxf(0.f, acc[b]*sc + sh);
    }
    __syncthreads();
    float* z2 = sb;
    if (t < 128) {
        float acc[16];
#pragma unroll
        for (int b = 0; b < 16; b++) acc[b] = bc2[t];
        for (int i = 0; i < 256; i++) {
            float w = Wc2[(size_t)i*128 + t];
#pragma unroll
            for (int b = 0; b < 16; b++) acc[b] += z1[b*256 + i] * w;
        }
        float m = 0.f;
#pragma unroll
        for (int b = 0; b < 16; b++) m += acc[b];
        m *= (1.f/16.f);
        float v = 0.f;
#pragma unroll
        for (int b = 0; b < 16; b++) { float d = acc[b]-m; v += d*d; }
        v *= (1.f/16.f);
        float sc = gc2[t] * rsqrtf(v + BN_EPS);
        float sh = hc2[t] - m * sc;
#pragma unroll
        for (int b = 0; b < 16; b++) z2[b*128 + t] = fmaxf(0.f, acc[b]*sc + sh);
    }
    __syncthreads();
    if (t < 40) {
        float acc[16];
#pragma unroll
        for (int b = 0; b < 16; b++) acc[b] = bc3[t];
        for (int i = 0; i < 128; i++) {
            float w = Wc3[(size_t)i*40 + t];
#pragma unroll
            for (int b = 0; b < 16; b++) acc[b] += z2[b*128 + i] * w;
        }
#pragma unroll
        for (int b = 0; b < 16; b++) out[b*40 + t] = acc[b];
    }
}

// ---------------- driver ----------------
extern "C" void kernel_launch(void* const* d_in, const int* in_sizes, int n_in,
                              void* d_out, int out_size) {
    (void)in_sizes; (void)n_in; (void)out_size;
    const float* x   = (const float*)d_in[0];
    const float* W1  = (const float*)d_in[1];
    const float* g1  = (const float*)d_in[2];
    const float* b1  = (const float*)d_in[3];
    const float* W2  = (const float*)d_in[4];
    const float* g2  = (const float*)d_in[5];
    const float* b2  = (const float*)d_in[6];
    const float* W3  = (const float*)d_in[7];
    const float* g3  = (const float*)d_in[8];
    const float* b3  = (const float*)d_in[9];
    const float* W4  = (const float*)d_in[10];
    const float* g4  = (const float*)d_in[11];
    const float* b4  = (const float*)d_in[12];
    const float* W5  = (const float*)d_in[13];
    const float* g5  = (const float*)d_in[14];
    const float* b5  = (const float*)d_in[15];
    const float* Wc1 = (const float*)d_in[16];
    const float* bc1 = (const float*)d_in[17];
    const float* gc1 = (const float*)d_in[18];
    const float* hc1 = (const float*)d_in[19];
    const float* Wc2 = (const float*)d_in[20];
    const float* bc2 = (const float*)d_in[21];
    const float* gc2 = (const float*)d_in[22];
    const float* hc2 = (const float*)d_in[23];
    const float* Wc3 = (const float*)d_in[24];
    const float* bc3 = (const float*)d_in[25];
    float* out = (float*)d_out;

    float *ybuf, *h0, *p1, *h1, *p2, *h2, *p3, *h3, *p4, *h4, *part0, *scale, *shift, *mdbuf;
    int* knn;
    cudaGetSymbolAddress((void**)&ybuf,  g_ybuf);
    cudaGetSymbolAddress((void**)&h0,    g_h0);
    cudaGetSymbolAddress((void**)&p1,    g_p1);
    cudaGetSymbolAddress((void**)&h1,    g_h1);
    cudaGetSymbolAddress((void**)&p2,    g_p2);
    cudaGetSymbolAddress((void**)&h2,    g_h2);
    cudaGetSymbolAddress((void**)&p3,    g_p3);
    cudaGetSymbolAddress((void**)&h3,    g_h3);
    cudaGetSymbolAddress((void**)&p4,    g_p4);
    cudaGetSymbolAddress((void**)&h4,    g_h4);
    cudaGetSymbolAddress((void**)&knn,   g_knn);
    cudaGetSymbolAddress((void**)&part0, g_part);
    cudaGetSymbolAddress((void**)&scale, g_scale);
    cudaGetSymbolAddress((void**)&shift, g_shift);
    cudaGetSymbolAddress((void**)&mdbuf, g_md);

    // carve scratch from ybuf (temporally disjoint with stage0's use of ybuf[0..2M))
    float* ymax  = ybuf;                       // <= 1,048,576 floats
    float* ymin  = ybuf + 1048576;
    float* part  = ybuf + 2097152;             // <= 2,097,152 floats (TD1)
    float* part2 = ybuf + 4194304;             // <= 65,536 floats
    const int NR = 64;

    const bool ov = g_sync.ok;
    cudaStream_t SB = ov ? g_sync.sb : 0;

    // ---- fork: segmented fps1 + rest of FPS chain on side stream ----
    if (ov) { cudaEventRecord(g_sync.fork, 0); cudaStreamWaitEvent(SB, g_sync.fork, 0); }
    fps_kernel<4096, 512><<<16, 512, 0, SB>>>(x, 1024, p1,   0,  256, mdbuf);
    if (ov) cudaEventRecord(g_sync.ea, SB);
    fps_kernel<4096, 512><<<16, 512, 0, SB>>>(x, 1024, p1, 256,  512, mdbuf);
    if (ov) cudaEventRecord(g_sync.eb, SB);
    fps_kernel<4096, 512><<<16, 512, 0, SB>>>(x, 1024, p1, 512,  768, mdbuf);
    if (ov) cudaEventRecord(g_sync.ec, SB);
    fps_kernel<4096, 512><<<16, 512, 0, SB>>>(x, 1024, p1, 768, 1024, mdbuf);
    if (ov) cudaEventRecord(g_sync.e1, SB);
    fps_kernel<1024, 256><<<16, 256, 0, SB>>>(p1, 256, p2, 0, 256, nullptr);
    if (ov) cudaEventRecord(g_sync.e2, SB);
    fps_kernel<256, 256><<<16, 256, 0, SB>>>(p2, 64, p3, 0, 64, nullptr);
    if (ov) cudaEventRecord(g_sync.e3, SB);
    fps_kernel<64, 64><<<16, 64, 0, SB>>>(p3, 16, p4, 0, 16, nullptr);
    if (ov) cudaEventRecord(g_sync.e4, SB);

    // ---- main stream: stage 0 (overlaps fps1 segments) ----
    s0_gemm<<<(16*4096*32 + 255)/256, 256>>>(x, W1, ybuf);
    stats_partial<<<512, 256>>>(ybuf, 16*4096, 32, part0);
    stats_final<<<1, 32>>>(part0, 512, 32, (float)(16*4096), g1, b1, scale, shift);
    normalize_kernel<<<(16*4096*32 + 255)/256, 256>>>(ybuf, scale, shift, 16*4096*32, 32, h0);

    // ---- TD1 chunks pipeline against fps1 segments via events (no device spinning) ----
    cudaEvent_t segev[4] = { g_sync.ea, g_sync.eb, g_sync.ec, g_sync.e1 };
    for (int s = 0; s < 4; s++) {
        if (ov) cudaStreamWaitEvent(0, segev[s], 0);
        int q0 = s * 256;
        knn_kernel<<<16*256, 128, 4096*4>>>(x, p1, 4096, 1024, knn, q0, 256);
        td_gemm_fused<<<16*256, 64, 16*35*4>>>(x, h0, p1, knn, W2, 4096, 1024, 32, 64,
                                               ymax, ymin, part, q0, 256);
    }
    stats_reduce<<<NR, 64>>>(part, 16*1024, 64, part2);
    stats_final<<<1, 64>>>(part2, NR, 64, (float)(16*1024*16), g2, b2, scale, shift);
    td_norm<<<(16*1024*64 + 255)/256, 256>>>(ymax, ymin, scale, shift, 16*1024*64, 64, h1);

    // ---- TD2: 1024 -> 256, C=64 -> D=128 ----
    if (ov) cudaStreamWaitEvent(0, g_sync.e2, 0);
    knn_kernel<<<16*256, 128, 1024*4>>>(p1, p2, 1024, 256, knn, 0, 256);
    td_gemm_fused<<<16*256, 128, 16*67*4>>>(p1, h1, p2, knn, W3, 1024, 256, 64, 128,
                                            ymax, ymin, part, 0, 256);
    stats_reduce<<<NR, 128>>>(part, 16*256, 128, part2);
    stats_final<<<1, 128>>>(part2, NR, 128, (float)(16*256*16), g3, b3, scale, shift);
    td_norm<<<(16*256*128 + 255)/256, 256>>>(ymax, ymin, scale, shift, 16*256*128, 128, h2);

    // ---- TD3: 256 -> 64, C=128 -> D=256 ----
    if (ov) cudaStreamWaitEvent(0, g_sync.e3, 0);
    knn_kernel<<<16*64, 128, 256*4>>>(p2, p3, 256, 64, knn, 0, 64);
    td_gemm_fused<<<16*64, 256, 16*131*4>>>(p2, h2, p3, knn, W4, 256, 64, 128, 256,
                                            ymax, ymin, part, 0, 64);
    stats_reduce<<<NR, 256>>>(part, 16*64, 256, part2);
    stats_final<<<1, 256>>>(part2, NR, 256, (float)(16*64*16), g4, b4, scale, shift);
    td_norm<<<(16*64*256 + 255)/256, 256>>>(ymax, ymin, scale, shift, 16*64*256, 256, h3);

    // ---- TD4: 64 -> 16, C=256 -> D=512 (join: waits last side-stream event) ----
    if (ov) cudaStreamWaitEvent(0, g_sync.e4, 0);
    knn_kernel<<<16*16, 128, 64*4>>>(p3, p4, 64, 16, knn, 0, 16);
    td_gemm_fused<<<16*16, 512, 16*259*4>>>(p3, h3, p4, knn, W5, 64, 16, 256, 512,
                                            ymax, ymin, part, 0, 16);
    stats_reduce<<<NR, 512>>>(part, 16*16, 512, part2);
    stats_final<<<1, 512>>>(part2, NR, 512, (float)(16*16*16), g5, b5, scale, shift);
    td_norm<<<(16*16*512 + 255)/256, 256>>>(ymax, ymin, scale, shift, 16*16*512, 512, h4);

    // ---- classifier head ----
    classifier_kernel<<<1, 256>>>(h4, Wc1, bc1, gc1, hc1, Wc2, bc2, gc2, hc2, Wc3, bc3, out);
}